// round 2
// baseline (speedup 1.0000x reference)
#include <cuda_runtime.h>
#include <math.h>

// ---------------------------------------------------------------------------
// HeatEquation1D: out = pad( u_inner @ (M^T)^100 )
//
// M = (I - 0.5aL)^-1 (I + 0.5aL), L = Dirichlet tridiag(1,-2,1), n=62.
// M is symmetric (polynomial in symmetric L), so (M^T)^100 = M^100 = P.
// Eigen-decomposition is closed form (discrete sine transform):
//   v_m[i] = sin(m*pi*(i+1)/63),  lam_m = -4 sin^2(m*pi/126)
//   mu_m = g_m^100,  g_m = (1 + 0.5a lam)/(1 - 0.5a lam),  a = 0.03969
// P[i][j] = (2/63) sum_m v_m[i] v_m[j] mu_m   (computed in fp64, ~0.24 MFLOP)
//
// P is embedded into a zero-padded 64x64 matrix g_P (interior at [1..62][1..62])
// so the main GEMM is a clean 524288x64 * 64x64 product and boundary columns
// 0 / 63 come out as exact zeros automatically.
// ---------------------------------------------------------------------------

#define PI_D 3.14159265358979323846

__device__ float g_P[64 * 64];

__global__ void build_P_kernel() {
    __shared__ float S[126];   // S[t] = sin(t*pi/63), exact period-126 table
    __shared__ float w[62];    // w[m-1] = mu_m * (2/63)

    const int j = threadIdx.x;   // 0..63  (padded column)
    const int i = blockIdx.x;    // 0..63  (padded row)

    for (int t = j; t < 126; t += 64) {
        S[t] = (float)sin((double)t * (PI_D / 63.0));
    }
    if (j < 62) {
        const int m = j + 1;
        double s   = sin((double)m * (PI_D / 126.0));
        double lam = -4.0 * s * s;
        double dx  = 1.0 / 63.0;
        double alpha = 0.01 * 0.001 / (dx * dx);   // nu*dt/dx^2 = 0.03969
        double g = (1.0 + 0.5 * alpha * lam) / (1.0 - 0.5 * alpha * lam);
        // g^100 = g^64 * g^32 * g^4
        double g2 = g * g, g4 = g2 * g2, g8 = g4 * g4;
        double g16 = g8 * g8, g32 = g16 * g16, g64 = g32 * g32;
        double mu = g64 * g32 * g4;
        w[j] = (float)(mu * (2.0 / 63.0));
    }
    __syncthreads();

    float val = 0.0f;
    if (i >= 1 && i <= 62 && j >= 1 && j <= 62) {
        float acc = 0.0f;
        #pragma unroll 2
        for (int m = 1; m <= 62; m++) {
            int t1 = (m * i) % 126;   // sin(m*i*pi/63) via period-126 table
            int t2 = (m * j) % 126;
            acc += S[t1] * S[t2] * w[m - 1];
        }
        val = acc;
    }
    g_P[i * 64 + j] = val;
}

// ---------------------------------------------------------------------------
// GEMM: Out[524288 x 64] = U[524288 x 64] * g_P[64 x 64]
// Rows 0 and 63 of g_P are zero, so we loop k = 1..62 and only stage those
// 62 B rows in shared memory.
//
// Block: 128 threads, tile 128(M) x 64(N) x 62(K).
// Thread: 8M x 8N with packed f32x2 accumulators (32 x fma.rn.f32x2 per k).
// As has row stride 65 so the 8-row-group scalar A loads hit banks
// {+0,+8,+16,+24} across the 4 ty-groups of a warp -> conflict free
// (8 same-ty threads broadcast). B loads are 16B vectors, broadcast across ty.
// Static smem = 128*65*4 + 62*64*4 = 49152 B (exactly 48 KB) -> 2 blocks/SM.
// ---------------------------------------------------------------------------

#define MT 128

__global__ __launch_bounds__(128, 2)
void gemm_kernel(const float* __restrict__ U, float* __restrict__ Out) {
    __shared__ float As[128 * 65];
    __shared__ float Bs[62 * 64];

    const int tid = threadIdx.x;
    const int tx  = tid & 7;    // 0..7  -> output cols j0 = tx*8
    const int ty  = tid >> 3;   // 0..15 -> rows r0 = ty*8

    const long long rowBase = (long long)blockIdx.x * MT;
    const float4* U4 = (const float4*)(U + rowBase * 64);

    // Stage A tile: 128 rows x 16 float4, 16 float4 per thread, coalesced.
    #pragma unroll
    for (int it = 0; it < 16; it++) {
        int idx = tid + it * 128;
        int r   = idx >> 4;
        int c4  = idx & 15;
        float4 v = U4[r * 16 + c4];
        float* dst = &As[r * 65 + c4 * 4];
        dst[0] = v.x; dst[1] = v.y; dst[2] = v.z; dst[3] = v.w;
    }

    // Stage B rows 1..62 of g_P (skip zero row 0): 62*16 = 992 float4.
    const float4* P4 = (const float4*)g_P;
    #pragma unroll
    for (int it = 0; it < 8; it++) {
        int idx = tid + it * 128;
        if (idx < 992) {
            ((float4*)Bs)[idx] = P4[16 + idx];
        }
    }
    __syncthreads();

    unsigned long long acc[8][4];
    #pragma unroll
    for (int i = 0; i < 8; i++)
        #pragma unroll
        for (int c = 0; c < 4; c++)
            acc[i][c] = 0ULL;   // packed {0.0f, 0.0f}

    const float* arow = As + ty * 8 * 65;

    #pragma unroll 2
    for (int k = 1; k <= 62; k++) {
        // B: 8 contiguous floats = 4 packed f32x2 operands
        const ulonglong2* brow =
            (const ulonglong2*)&Bs[(k - 1) * 64 + tx * 8];
        ulonglong2 bA = brow[0];
        ulonglong2 bB = brow[1];
        unsigned long long bp0 = bA.x, bp1 = bA.y, bp2 = bB.x, bp3 = bB.y;

        #pragma unroll
        for (int i = 0; i < 8; i++) {
            float a = arow[i * 65 + k];
            unsigned long long ad;
            asm("mov.b64 %0, {%1, %1};" : "=l"(ad) : "r"(__float_as_uint(a)));
            asm("fma.rn.f32x2 %0, %1, %2, %0;" : "+l"(acc[i][0]) : "l"(ad), "l"(bp0));
            asm("fma.rn.f32x2 %0, %1, %2, %0;" : "+l"(acc[i][1]) : "l"(ad), "l"(bp1));
            asm("fma.rn.f32x2 %0, %1, %2, %0;" : "+l"(acc[i][2]) : "l"(ad), "l"(bp2));
            asm("fma.rn.f32x2 %0, %1, %2, %0;" : "+l"(acc[i][3]) : "l"(ad), "l"(bp3));
        }
    }

    // Epilogue: each thread writes 8 rows x 8 cols (2 x 16B stores per row).
    float* orow = Out + rowBase * 64;
    #pragma unroll
    for (int i = 0; i < 8; i++) {
        int r = ty * 8 + i;
        ulonglong2* dst = (ulonglong2*)(orow + r * 64 + tx * 8);
        ulonglong2 v0, v1;
        v0.x = acc[i][0]; v0.y = acc[i][1];
        v1.x = acc[i][2]; v1.y = acc[i][3];
        dst[0] = v0;
        dst[1] = v1;
    }
}

extern "C" void kernel_launch(void* const* d_in, const int* in_sizes, int n_in,
                              void* d_out, int out_size) {
    (void)in_sizes; (void)n_in; (void)out_size;
    const float* U = (const float*)d_in[0];   // u0 [524288 x 64] fp32
    float* Out = (float*)d_out;               // [524288 x 64] fp32

    build_P_kernel<<<64, 64>>>();
    gemm_kernel<<<524288 / MT, 128>>>(U, Out);
}